// round 1
// baseline (speedup 1.0000x reference)
#include <cuda_runtime.h>
#include <cstdint>

#define D 64
#define NMAX 100000
#define EMAX 1600000
#define SCALE 0.125f  // D^-0.5 = 1/8

// Scratch (device globals: allocation-free per harness rules)
__device__ float g_Q[NMAX * D];
__device__ float g_K[NMAX * D];
__device__ float g_V[NMAX * D];
__device__ float g_num[NMAX * D];
__device__ float g_denom[NMAX];

// ---------------------------------------------------------------------------
// Zero the accumulators (required every launch: graph replays).
// ---------------------------------------------------------------------------
__global__ void zero_kernel(int N) {
    const float4 z = make_float4(0.f, 0.f, 0.f, 0.f);
    int total4 = N * D / 4;
    for (int i = blockIdx.x * blockDim.x + threadIdx.x; i < total4;
         i += gridDim.x * blockDim.x) {
        reinterpret_cast<float4*>(g_num)[i] = z;
    }
    for (int i = blockIdx.x * blockDim.x + threadIdx.x; i < N;
         i += gridDim.x * blockDim.x) {
        g_denom[i] = 0.f;
    }
}

// ---------------------------------------------------------------------------
// Q,K projection: g_Q = x@Wq, g_K = x@Wk.
// Block: 256 threads; 16 threads per row (each owns 4 output columns).
// W matrices staged in smem once per block; grid-stride over rows.
// ---------------------------------------------------------------------------
__global__ void qk_kernel(const float* __restrict__ x,
                          const float* __restrict__ Wq,
                          const float* __restrict__ Wk, int N) {
    __shared__ float4 sWq[D * 16];
    __shared__ float4 sWk[D * 16];
    __shared__ float sx[16][D + 4];  // +4 pad kills 2-way bank conflict, keeps 16B align

    for (int i = threadIdx.x; i < D * 16; i += blockDim.x) {
        sWq[i] = reinterpret_cast<const float4*>(Wq)[i];
        sWk[i] = reinterpret_cast<const float4*>(Wk)[i];
    }
    __syncthreads();

    const int cq = threadIdx.x & 15;   // float4 column group 0..15
    const int rl = threadIdx.x >> 4;   // local row 0..15

    for (int row0 = blockIdx.x * 16; row0 < N; row0 += gridDim.x * 16) {
        int row = row0 + rl;
        bool valid = row < N;
        if (valid) {
            float4 xr = reinterpret_cast<const float4*>(x + (size_t)row * D)[cq];
            *reinterpret_cast<float4*>(&sx[rl][cq * 4]) = xr;
        }
        __syncthreads();
        float4 qa = make_float4(0.f, 0.f, 0.f, 0.f);
        float4 ka = make_float4(0.f, 0.f, 0.f, 0.f);
#pragma unroll
        for (int kk = 0; kk < D; kk++) {
            float xv = sx[rl][kk];
            float4 wq = sWq[kk * 16 + cq];
            float4 wk = sWk[kk * 16 + cq];
            qa.x = fmaf(xv, wq.x, qa.x); qa.y = fmaf(xv, wq.y, qa.y);
            qa.z = fmaf(xv, wq.z, qa.z); qa.w = fmaf(xv, wq.w, qa.w);
            ka.x = fmaf(xv, wk.x, ka.x); ka.y = fmaf(xv, wk.y, ka.y);
            ka.z = fmaf(xv, wk.z, ka.z); ka.w = fmaf(xv, wk.w, ka.w);
        }
        if (valid) {
            reinterpret_cast<float4*>(g_Q + (size_t)row * D)[cq] = qa;
            reinterpret_cast<float4*>(g_K + (size_t)row * D)[cq] = ka;
        }
        __syncthreads();
    }
}

// ---------------------------------------------------------------------------
// V projection: g_V = x@Wv.
// ---------------------------------------------------------------------------
__global__ void v_kernel(const float* __restrict__ x,
                         const float* __restrict__ Wv, int N) {
    __shared__ float4 sW[D * 16];
    __shared__ float sx[16][D + 4];

    for (int i = threadIdx.x; i < D * 16; i += blockDim.x)
        sW[i] = reinterpret_cast<const float4*>(Wv)[i];
    __syncthreads();

    const int cq = threadIdx.x & 15;
    const int rl = threadIdx.x >> 4;

    for (int row0 = blockIdx.x * 16; row0 < N; row0 += gridDim.x * 16) {
        int row = row0 + rl;
        bool valid = row < N;
        if (valid) {
            float4 xr = reinterpret_cast<const float4*>(x + (size_t)row * D)[cq];
            *reinterpret_cast<float4*>(&sx[rl][cq * 4]) = xr;
        }
        __syncthreads();
        float4 va = make_float4(0.f, 0.f, 0.f, 0.f);
#pragma unroll
        for (int kk = 0; kk < D; kk++) {
            float xv = sx[rl][kk];
            float4 w = sW[kk * 16 + cq];
            va.x = fmaf(xv, w.x, va.x); va.y = fmaf(xv, w.y, va.y);
            va.z = fmaf(xv, w.z, va.z); va.w = fmaf(xv, w.w, va.w);
        }
        if (valid)
            reinterpret_cast<float4*>(g_V + (size_t)row * D)[cq] = va;
        __syncthreads();
    }
}

// ---------------------------------------------------------------------------
// Edge pass: 8 threads per edge.
//   s = <Q[recv], K[send]> * SCALE ; p = exp(s)
//   denom[recv] += p ; num[recv] += p * V[send]   (vector red.global)
// No segment-max needed: logits are ~N(0,1), exp() is safe in fp32 and the
// softmax ratio is identical.
// ---------------------------------------------------------------------------
__global__ void edge_kernel(const int* __restrict__ ei, int E) {
    int idx = blockIdx.x * blockDim.x + threadIdx.x;
    int e = idx >> 3;
    int l = idx & 7;
    bool live = e < E;
    int ec = live ? e : 0;

    int snd = __ldg(&ei[ec]);       // edge_index[0] = sender
    int rcv = __ldg(&ei[E + ec]);   // edge_index[1] = receiver

    const float4* Q4 = reinterpret_cast<const float4*>(g_Q + (size_t)rcv * D);
    const float4* K4 = reinterpret_cast<const float4*>(g_K + (size_t)snd * D);
    float4 q0 = Q4[l * 2], q1 = Q4[l * 2 + 1];
    float4 k0 = K4[l * 2], k1 = K4[l * 2 + 1];

    float d = q0.x * k0.x + q0.y * k0.y + q0.z * k0.z + q0.w * k0.w
            + q1.x * k1.x + q1.y * k1.y + q1.z * k1.z + q1.w * k1.w;
    // reduce across the 8 lanes of this edge (xor stays within the octet)
    d += __shfl_xor_sync(0xffffffffu, d, 1);
    d += __shfl_xor_sync(0xffffffffu, d, 2);
    d += __shfl_xor_sync(0xffffffffu, d, 4);

    float p = __expf(d * SCALE);

    const float4* V4 = reinterpret_cast<const float4*>(g_V + (size_t)snd * D);
    float4 v0 = V4[l * 2], v1 = V4[l * 2 + 1];

    if (live) {
        if (l == 0) atomicAdd(&g_denom[rcv], p);
        float* dst = g_num + (size_t)rcv * D + l * 8;
        asm volatile("red.global.v4.f32.add [%0], {%1,%2,%3,%4};" ::"l"(dst),
                     "f"(p * v0.x), "f"(p * v0.y), "f"(p * v0.z), "f"(p * v0.w)
                     : "memory");
        asm volatile("red.global.v4.f32.add [%0], {%1,%2,%3,%4};" ::"l"(dst + 4),
                     "f"(p * v1.x), "f"(p * v1.y), "f"(p * v1.z), "f"(p * v1.w)
                     : "memory");
    }
}

// ---------------------------------------------------------------------------
// Output: out = x + (num/denom) @ Wo  (zero for empty receivers).
// ---------------------------------------------------------------------------
__global__ void out_kernel(const float* __restrict__ x,
                           const float* __restrict__ Wo,
                           float* __restrict__ out, int N) {
    __shared__ float4 sW[D * 16];
    __shared__ float sh[16][D + 4];

    for (int i = threadIdx.x; i < D * 16; i += blockDim.x)
        sW[i] = reinterpret_cast<const float4*>(Wo)[i];
    __syncthreads();

    const int cq = threadIdx.x & 15;
    const int rl = threadIdx.x >> 4;

    for (int row0 = blockIdx.x * 16; row0 < N; row0 += gridDim.x * 16) {
        int row = row0 + rl;
        bool valid = row < N;
        if (valid) {
            float dn = g_denom[row];
            float inv = dn > 0.f ? 1.0f / dn : 0.f;
            float4 nm = reinterpret_cast<const float4*>(g_num + (size_t)row * D)[cq];
            float4 h4 = make_float4(nm.x * inv, nm.y * inv, nm.z * inv, nm.w * inv);
            *reinterpret_cast<float4*>(&sh[rl][cq * 4]) = h4;
        }
        __syncthreads();
        float4 acc = make_float4(0.f, 0.f, 0.f, 0.f);
#pragma unroll
        for (int kk = 0; kk < D; kk++) {
            float hv = sh[rl][kk];
            float4 w = sW[kk * 16 + cq];
            acc.x = fmaf(hv, w.x, acc.x); acc.y = fmaf(hv, w.y, acc.y);
            acc.z = fmaf(hv, w.z, acc.z); acc.w = fmaf(hv, w.w, acc.w);
        }
        if (valid) {
            float4 xr = reinterpret_cast<const float4*>(x + (size_t)row * D)[cq];
            float4 o = make_float4(xr.x + acc.x, xr.y + acc.y,
                                   xr.z + acc.z, xr.w + acc.w);
            reinterpret_cast<float4*>(out + (size_t)row * D)[cq] = o;
        }
        __syncthreads();
    }
}

// ---------------------------------------------------------------------------
extern "C" void kernel_launch(void* const* d_in, const int* in_sizes, int n_in,
                              void* d_out, int out_size) {
    const float* x  = (const float*)d_in[0];
    const int*   ei = (const int*)d_in[1];
    const float* Wq = (const float*)d_in[2];
    const float* Wk = (const float*)d_in[3];
    const float* Wv = (const float*)d_in[4];
    const float* Wo = (const float*)d_in[5];
    float* out = (float*)d_out;

    int N = in_sizes[0] / D;
    int E = in_sizes[1] / 2;

    const int GEMM_BLOCKS = 592;  // 4 per SM

    zero_kernel<<<1184, 256>>>(N);
    qk_kernel<<<GEMM_BLOCKS, 256>>>(x, Wq, Wk, N);
    v_kernel<<<GEMM_BLOCKS, 256>>>(x, Wv, N);
    int edge_threads = E * 8;
    edge_kernel<<<(edge_threads + 255) / 256, 256>>>(ei, E);
    out_kernel<<<GEMM_BLOCKS, 256>>>(x, Wo, out, N);
}

// round 2
// speedup vs baseline: 1.1529x; 1.1529x over previous
#include <cuda_runtime.h>
#include <cstdint>

#define D 64
#define NMAX 100000
#define EMAX 1600000
#define SCALE 0.125f  // D^-0.5 = 1/8

// Scratch (device globals: allocation-free per harness rules)
__device__ float g_Q[NMAX * D];
__device__ float g_K[NMAX * D];
__device__ float g_V[NMAX * D];
__device__ float g_num[NMAX * D];
__device__ float g_denom[NMAX];

// ---------------------------------------------------------------------------
// Zero the accumulators (required every launch: graph replays).
// ---------------------------------------------------------------------------
__global__ void zero_kernel(int N) {
    const float4 z = make_float4(0.f, 0.f, 0.f, 0.f);
    int total4 = N * D / 4;
    for (int i = blockIdx.x * blockDim.x + threadIdx.x; i < total4;
         i += gridDim.x * blockDim.x) {
        reinterpret_cast<float4*>(g_num)[i] = z;
    }
    for (int i = blockIdx.x * blockDim.x + threadIdx.x; i < N;
         i += gridDim.x * blockDim.x) {
        g_denom[i] = 0.f;
    }
}

// ---------------------------------------------------------------------------
// Fused QKV projection with register blocking.
// Block = 256 threads, tile = 128 rows x 64 cols.
// Each thread owns a 4-row x 8-col register tile (32 accumulators per pass),
// runs three passes (Q, K, V) over the same smem-staged x tile.
// Per kk per thread: 4 x-scalars from smem (16B, conflict-free via pitch 65)
// + 2 float4 W loads via __ldg (L1-resident, warp-deduped) -> 32 FMA.
// ---------------------------------------------------------------------------
__global__ void __launch_bounds__(256) qkv_kernel(
    const float* __restrict__ x,
    const float* __restrict__ Wq,
    const float* __restrict__ Wk,
    const float* __restrict__ Wv, int N) {
    __shared__ float sx[128][65];  // 65-float pitch: rows 4 apart land 4 banks apart

    const int tile0 = blockIdx.x * 128;

    // Stage x tile (128 rows x 64 cols) into smem, zero-padded past N.
    for (int i = threadIdx.x; i < 128 * 16; i += 256) {
        int row = i >> 4;
        int c4 = i & 15;
        int grow = tile0 + row;
        float4 v = make_float4(0.f, 0.f, 0.f, 0.f);
        if (grow < N) v = reinterpret_cast<const float4*>(x + (size_t)grow * D)[c4];
        float* dst = &sx[row][c4 * 4];
        dst[0] = v.x; dst[1] = v.y; dst[2] = v.z; dst[3] = v.w;
    }
    __syncthreads();

    const int j = (threadIdx.x & 7) * 8;        // 8 output cols
    const int r0 = (threadIdx.x >> 3) * 4;      // 4 rows

    const float* Ws[3] = {Wq, Wk, Wv};
    float* Gs[3] = {g_Q, g_K, g_V};

#pragma unroll
    for (int p = 0; p < 3; p++) {
        const float* W = Ws[p];
        float* G = Gs[p];
        float acc[4][8];
#pragma unroll
        for (int rr = 0; rr < 4; rr++)
#pragma unroll
            for (int cc = 0; cc < 8; cc++) acc[rr][cc] = 0.f;

#pragma unroll 8
        for (int kk = 0; kk < D; kk++) {
            float4 w0 = __ldg(reinterpret_cast<const float4*>(W + kk * D + j));
            float4 w1 = __ldg(reinterpret_cast<const float4*>(W + kk * D + j + 4));
            float xv0 = sx[r0 + 0][kk];
            float xv1 = sx[r0 + 1][kk];
            float xv2 = sx[r0 + 2][kk];
            float xv3 = sx[r0 + 3][kk];
#define FMA_ROW(rr, xv)                                                \
            acc[rr][0] = fmaf(xv, w0.x, acc[rr][0]);                   \
            acc[rr][1] = fmaf(xv, w0.y, acc[rr][1]);                   \
            acc[rr][2] = fmaf(xv, w0.z, acc[rr][2]);                   \
            acc[rr][3] = fmaf(xv, w0.w, acc[rr][3]);                   \
            acc[rr][4] = fmaf(xv, w1.x, acc[rr][4]);                   \
            acc[rr][5] = fmaf(xv, w1.y, acc[rr][5]);                   \
            acc[rr][6] = fmaf(xv, w1.z, acc[rr][6]);                   \
            acc[rr][7] = fmaf(xv, w1.w, acc[rr][7]);
            FMA_ROW(0, xv0)
            FMA_ROW(1, xv1)
            FMA_ROW(2, xv2)
            FMA_ROW(3, xv3)
#undef FMA_ROW
        }

#pragma unroll
        for (int rr = 0; rr < 4; rr++) {
            int grow = tile0 + r0 + rr;
            if (grow < N) {
                float4* dst = reinterpret_cast<float4*>(G + (size_t)grow * D + j);
                dst[0] = make_float4(acc[rr][0], acc[rr][1], acc[rr][2], acc[rr][3]);
                dst[1] = make_float4(acc[rr][4], acc[rr][5], acc[rr][6], acc[rr][7]);
            }
        }
    }
}

// ---------------------------------------------------------------------------
// Edge pass: 8 threads per edge.
//   s = <Q[recv], K[send]> * SCALE ; p = exp(s)
//   denom[recv] += p ; num[recv] += p * V[send]   (vector red.global)
// No segment-max needed: logits are ~N(0,1), exp() is safe in fp32 and the
// softmax ratio is identical.
// ---------------------------------------------------------------------------
__global__ void edge_kernel(const int* __restrict__ ei, int E) {
    int idx = blockIdx.x * blockDim.x + threadIdx.x;
    int e = idx >> 3;
    int l = idx & 7;
    bool live = e < E;
    int ec = live ? e : 0;

    int snd = __ldg(&ei[ec]);       // edge_index[0] = sender
    int rcv = __ldg(&ei[E + ec]);   // edge_index[1] = receiver

    const float4* Q4 = reinterpret_cast<const float4*>(g_Q + (size_t)rcv * D);
    const float4* K4 = reinterpret_cast<const float4*>(g_K + (size_t)snd * D);
    float4 q0 = Q4[l * 2], q1 = Q4[l * 2 + 1];
    float4 k0 = K4[l * 2], k1 = K4[l * 2 + 1];

    float d = q0.x * k0.x + q0.y * k0.y + q0.z * k0.z + q0.w * k0.w
            + q1.x * k1.x + q1.y * k1.y + q1.z * k1.z + q1.w * k1.w;
    d += __shfl_xor_sync(0xffffffffu, d, 1);
    d += __shfl_xor_sync(0xffffffffu, d, 2);
    d += __shfl_xor_sync(0xffffffffu, d, 4);

    float p = __expf(d * SCALE);

    const float4* V4 = reinterpret_cast<const float4*>(g_V + (size_t)snd * D);
    float4 v0 = V4[l * 2], v1 = V4[l * 2 + 1];

    if (live) {
        if (l == 0) atomicAdd(&g_denom[rcv], p);
        float* dst = g_num + (size_t)rcv * D + l * 8;
        asm volatile("red.global.v4.f32.add [%0], {%1,%2,%3,%4};" ::"l"(dst),
                     "f"(p * v0.x), "f"(p * v0.y), "f"(p * v0.z), "f"(p * v0.w)
                     : "memory");
        asm volatile("red.global.v4.f32.add [%0], {%1,%2,%3,%4};" ::"l"(dst + 4),
                     "f"(p * v1.x), "f"(p * v1.y), "f"(p * v1.z), "f"(p * v1.w)
                     : "memory");
    }
}

// ---------------------------------------------------------------------------
// Output: out = x + (num/denom) @ Wo  (zero for empty receivers).
// Same register-blocked structure as qkv_kernel, single pass.
// ---------------------------------------------------------------------------
__global__ void __launch_bounds__(256) out_kernel(
    const float* __restrict__ x,
    const float* __restrict__ Wo,
    float* __restrict__ out, int N) {
    __shared__ float sh[128][65];

    const int tile0 = blockIdx.x * 128;

    // Stage h = num/denom tile into smem.
    for (int i = threadIdx.x; i < 128 * 16; i += 256) {
        int row = i >> 4;
        int c4 = i & 15;
        int grow = tile0 + row;
        float4 v = make_float4(0.f, 0.f, 0.f, 0.f);
        if (grow < N) {
            float dn = g_denom[grow];
            float inv = dn > 0.f ? 1.0f / dn : 0.f;
            float4 nm = reinterpret_cast<const float4*>(g_num + (size_t)grow * D)[c4];
            v = make_float4(nm.x * inv, nm.y * inv, nm.z * inv, nm.w * inv);
        }
        float* dst = &sh[row][c4 * 4];
        dst[0] = v.x; dst[1] = v.y; dst[2] = v.z; dst[3] = v.w;
    }
    __syncthreads();

    const int j = (threadIdx.x & 7) * 8;
    const int r0 = (threadIdx.x >> 3) * 4;

    float acc[4][8];
#pragma unroll
    for (int rr = 0; rr < 4; rr++)
#pragma unroll
        for (int cc = 0; cc < 8; cc++) acc[rr][cc] = 0.f;

#pragma unroll 8
    for (int kk = 0; kk < D; kk++) {
        float4 w0 = __ldg(reinterpret_cast<const float4*>(Wo + kk * D + j));
        float4 w1 = __ldg(reinterpret_cast<const float4*>(Wo + kk * D + j + 4));
        float xv0 = sh[r0 + 0][kk];
        float xv1 = sh[r0 + 1][kk];
        float xv2 = sh[r0 + 2][kk];
        float xv3 = sh[r0 + 3][kk];
#define FMA_ROW(rr, xv)                                                \
        acc[rr][0] = fmaf(xv, w0.x, acc[rr][0]);                       \
        acc[rr][1] = fmaf(xv, w0.y, acc[rr][1]);                       \
        acc[rr][2] = fmaf(xv, w0.z, acc[rr][2]);                       \
        acc[rr][3] = fmaf(xv, w0.w, acc[rr][3]);                       \
        acc[rr][4] = fmaf(xv, w1.x, acc[rr][4]);                       \
        acc[rr][5] = fmaf(xv, w1.y, acc[rr][5]);                       \
        acc[rr][6] = fmaf(xv, w1.z, acc[rr][6]);                       \
        acc[rr][7] = fmaf(xv, w1.w, acc[rr][7]);
        FMA_ROW(0, xv0)
        FMA_ROW(1, xv1)
        FMA_ROW(2, xv2)
        FMA_ROW(3, xv3)
#undef FMA_ROW
    }

#pragma unroll
    for (int rr = 0; rr < 4; rr++) {
        int grow = tile0 + r0 + rr;
        if (grow < N) {
            const float4* xr = reinterpret_cast<const float4*>(x + (size_t)grow * D + j);
            float4 x0 = xr[0], x1 = xr[1];
            float4* dst = reinterpret_cast<float4*>(out + (size_t)grow * D + j);
            dst[0] = make_float4(x0.x + acc[rr][0], x0.y + acc[rr][1],
                                 x0.z + acc[rr][2], x0.w + acc[rr][3]);
            dst[1] = make_float4(x1.x + acc[rr][4], x1.y + acc[rr][5],
                                 x1.z + acc[rr][6], x1.w + acc[rr][7]);
        }
    }
}

// ---------------------------------------------------------------------------
extern "C" void kernel_launch(void* const* d_in, const int* in_sizes, int n_in,
                              void* d_out, int out_size) {
    const float* x  = (const float*)d_in[0];
    const int*   ei = (const int*)d_in[1];
    const float* Wq = (const float*)d_in[2];
    const float* Wk = (const float*)d_in[3];
    const float* Wv = (const float*)d_in[4];
    const float* Wo = (const float*)d_in[5];
    float* out = (float*)d_out;

    int N = in_sizes[0] / D;
    int E = in_sizes[1] / 2;

    int tiles = (N + 127) / 128;

    zero_kernel<<<1184, 256>>>(N);
    qkv_kernel<<<tiles, 256>>>(x, Wq, Wk, Wv, N);
    int edge_threads = E * 8;
    edge_kernel<<<(edge_threads + 255) / 256, 256>>>(ei, E);
    out_kernel<<<tiles, 256>>>(x, Wo, out, N);
}

// round 3
// speedup vs baseline: 1.3019x; 1.1292x over previous
#include <cuda_runtime.h>
#include <cstdint>

#define D 64
#define NMAX 100000
#define EMAX 1600000
#define SCALE 0.125f  // D^-0.5 = 1/8

typedef unsigned long long u64;

// Scratch (device globals: allocation-free per harness rules)
__device__ float g_Q[NMAX * D];
__device__ float g_K[NMAX * D];
__device__ float g_V[NMAX * D];
__device__ float g_num[NMAX * D];
__device__ float g_denom[NMAX];

// ---- f32x2 packed-FMA helpers (sm_100+; double-rate fp32) -----------------
__device__ __forceinline__ u64 pk2(float lo, float hi) {
    u64 r; asm("mov.b64 %0, {%1,%2};" : "=l"(r) : "f"(lo), "f"(hi)); return r;
}
__device__ __forceinline__ void fma2(u64& d, u64 a, u64 b) {
    asm("fma.rn.f32x2 %0, %1, %2, %0;" : "+l"(d) : "l"(a), "l"(b));
}
__device__ __forceinline__ float2 upk(u64 v) {
    float2 f; asm("mov.b64 {%0,%1}, %2;" : "=f"(f.x), "=f"(f.y) : "l"(v)); return f;
}

// ---------------------------------------------------------------------------
// Zero the accumulators (required every launch: graph replays).
// ---------------------------------------------------------------------------
__global__ void zero_kernel(int N) {
    const float4 z = make_float4(0.f, 0.f, 0.f, 0.f);
    int total4 = N * D / 4;
    for (int i = blockIdx.x * blockDim.x + threadIdx.x; i < total4;
         i += gridDim.x * blockDim.x) {
        reinterpret_cast<float4*>(g_num)[i] = z;
    }
    for (int i = blockIdx.x * blockDim.x + threadIdx.x; i < N;
         i += gridDim.x * blockDim.x) {
        g_denom[i] = 0.f;
    }
}

// ---------------------------------------------------------------------------
// Fused QKV projection. 64-row tile, 128 threads.
// Each thread: 4 rows x 8 cols, accumulated as 4x4 f32x2 col-pairs.
// W staged in smem (one 16KB buffer reused across the Q/K/V passes);
// x tile staged once. Per kk: 4 LDS.32 (x, bcast) + 2 LDS.128 (W) +
// 4 dup-movs + 16 FFMA2 -> fma-pipe bound.
// ---------------------------------------------------------------------------
__global__ void __launch_bounds__(128) qkv_kernel(
    const float* __restrict__ x,
    const float* __restrict__ Wq,
    const float* __restrict__ Wk,
    const float* __restrict__ Wv, int N) {
    __shared__ float sx[64][65];
    __shared__ float4 sW[D * 16];

    const int tile0 = blockIdx.x * 64;

    for (int i = threadIdx.x; i < 64 * 16; i += 128) {
        int row = i >> 4;
        int c4 = i & 15;
        int grow = tile0 + row;
        float4 v = make_float4(0.f, 0.f, 0.f, 0.f);
        if (grow < N) v = reinterpret_cast<const float4*>(x + (size_t)grow * D)[c4];
        float* dst = &sx[row][c4 * 4];
        dst[0] = v.x; dst[1] = v.y; dst[2] = v.z; dst[3] = v.w;
    }

    const int jq = (threadIdx.x & 7) * 2;   // float4 index of first col group
    const int r0 = (threadIdx.x >> 3) * 4;  // first of 4 rows

    const float* Ws[3] = {Wq, Wk, Wv};
    float* Gs[3] = {g_Q, g_K, g_V};

#pragma unroll
    for (int p = 0; p < 3; p++) {
        __syncthreads();  // covers sx staging (p=0) / prior pass sW reads (p>0)
        for (int i = threadIdx.x; i < D * 16; i += 128)
            sW[i] = __ldg(reinterpret_cast<const float4*>(Ws[p]) + i);
        __syncthreads();

        u64 acc[4][4];
#pragma unroll
        for (int rr = 0; rr < 4; rr++)
#pragma unroll
            for (int cp = 0; cp < 4; cp++) acc[rr][cp] = 0ull;

#pragma unroll 8
        for (int kk = 0; kk < D; kk++) {
            float4 w0 = sW[kk * 16 + jq];
            float4 w1 = sW[kk * 16 + jq + 1];
            u64 wp0 = pk2(w0.x, w0.y);
            u64 wp1 = pk2(w0.z, w0.w);
            u64 wp2 = pk2(w1.x, w1.y);
            u64 wp3 = pk2(w1.z, w1.w);
            float xv0 = sx[r0 + 0][kk];
            float xv1 = sx[r0 + 1][kk];
            float xv2 = sx[r0 + 2][kk];
            float xv3 = sx[r0 + 3][kk];
            u64 xd0 = pk2(xv0, xv0);
            u64 xd1 = pk2(xv1, xv1);
            u64 xd2 = pk2(xv2, xv2);
            u64 xd3 = pk2(xv3, xv3);
            fma2(acc[0][0], xd0, wp0); fma2(acc[0][1], xd0, wp1);
            fma2(acc[0][2], xd0, wp2); fma2(acc[0][3], xd0, wp3);
            fma2(acc[1][0], xd1, wp0); fma2(acc[1][1], xd1, wp1);
            fma2(acc[1][2], xd1, wp2); fma2(acc[1][3], xd1, wp3);
            fma2(acc[2][0], xd2, wp0); fma2(acc[2][1], xd2, wp1);
            fma2(acc[2][2], xd2, wp2); fma2(acc[2][3], xd2, wp3);
            fma2(acc[3][0], xd3, wp0); fma2(acc[3][1], xd3, wp1);
            fma2(acc[3][2], xd3, wp2); fma2(acc[3][3], xd3, wp3);
        }

        float* G = Gs[p];
#pragma unroll
        for (int rr = 0; rr < 4; rr++) {
            int grow = tile0 + r0 + rr;
            if (grow < N) {
                float2 a0 = upk(acc[rr][0]), a1 = upk(acc[rr][1]);
                float2 a2 = upk(acc[rr][2]), a3 = upk(acc[rr][3]);
                float4* dst = reinterpret_cast<float4*>(G + (size_t)grow * D + jq * 4);
                dst[0] = make_float4(a0.x, a0.y, a1.x, a1.y);
                dst[1] = make_float4(a2.x, a2.y, a3.x, a3.y);
            }
        }
    }
}

// ---------------------------------------------------------------------------
// Edge pass: 8 threads per edge (unchanged; at the LTS wall).
//   s = <Q[recv], K[send]> * SCALE ; p = exp(s)
//   denom[recv] += p ; num[recv] += p * V[send]   (vector red.global)
// No segment-max needed: logits are ~N(0,1); exp() is safe in fp32.
// ---------------------------------------------------------------------------
__global__ void edge_kernel(const int* __restrict__ ei, int E) {
    int idx = blockIdx.x * blockDim.x + threadIdx.x;
    int e = idx >> 3;
    int l = idx & 7;
    bool live = e < E;
    int ec = live ? e : 0;

    int snd = __ldg(&ei[ec]);       // edge_index[0] = sender
    int rcv = __ldg(&ei[E + ec]);   // edge_index[1] = receiver

    const float4* Q4 = reinterpret_cast<const float4*>(g_Q + (size_t)rcv * D);
    const float4* K4 = reinterpret_cast<const float4*>(g_K + (size_t)snd * D);
    float4 q0 = Q4[l * 2], q1 = Q4[l * 2 + 1];
    float4 k0 = K4[l * 2], k1 = K4[l * 2 + 1];

    float d = q0.x * k0.x + q0.y * k0.y + q0.z * k0.z + q0.w * k0.w
            + q1.x * k1.x + q1.y * k1.y + q1.z * k1.z + q1.w * k1.w;
    d += __shfl_xor_sync(0xffffffffu, d, 1);
    d += __shfl_xor_sync(0xffffffffu, d, 2);
    d += __shfl_xor_sync(0xffffffffu, d, 4);

    float p = __expf(d * SCALE);

    const float4* V4 = reinterpret_cast<const float4*>(g_V + (size_t)snd * D);
    float4 v0 = V4[l * 2], v1 = V4[l * 2 + 1];

    if (live) {
        if (l == 0) atomicAdd(&g_denom[rcv], p);
        float* dst = g_num + (size_t)rcv * D + l * 8;
        asm volatile("red.global.v4.f32.add [%0], {%1,%2,%3,%4};" ::"l"(dst),
                     "f"(p * v0.x), "f"(p * v0.y), "f"(p * v0.z), "f"(p * v0.w)
                     : "memory");
        asm volatile("red.global.v4.f32.add [%0], {%1,%2,%3,%4};" ::"l"(dst + 4),
                     "f"(p * v1.x), "f"(p * v1.y), "f"(p * v1.z), "f"(p * v1.w)
                     : "memory");
    }
}

// ---------------------------------------------------------------------------
// Output: out = x + (num/denom) @ Wo. Same f32x2 structure as qkv, one pass.
// ---------------------------------------------------------------------------
__global__ void __launch_bounds__(128) out_kernel(
    const float* __restrict__ x,
    const float* __restrict__ Wo,
    float* __restrict__ out, int N) {
    __shared__ float sh[64][65];
    __shared__ float4 sW[D * 16];

    const int tile0 = blockIdx.x * 64;

    for (int i = threadIdx.x; i < 64 * 16; i += 128) {
        int row = i >> 4;
        int c4 = i & 15;
        int grow = tile0 + row;
        float4 v = make_float4(0.f, 0.f, 0.f, 0.f);
        if (grow < N) {
            float dn = g_denom[grow];
            float inv = dn > 0.f ? 1.0f / dn : 0.f;
            float4 nm = reinterpret_cast<const float4*>(g_num + (size_t)grow * D)[c4];
            v = make_float4(nm.x * inv, nm.y * inv, nm.z * inv, nm.w * inv);
        }
        float* dst = &sh[row][c4 * 4];
        dst[0] = v.x; dst[1] = v.y; dst[2] = v.z; dst[3] = v.w;
    }
    for (int i = threadIdx.x; i < D * 16; i += 128)
        sW[i] = __ldg(reinterpret_cast<const float4*>(Wo) + i);
    __syncthreads();

    const int jq = (threadIdx.x & 7) * 2;
    const int r0 = (threadIdx.x >> 3) * 4;

    u64 acc[4][4];
#pragma unroll
    for (int rr = 0; rr < 4; rr++)
#pragma unroll
        for (int cp = 0; cp < 4; cp++) acc[rr][cp] = 0ull;

#pragma unroll 8
    for (int kk = 0; kk < D; kk++) {
        float4 w0 = sW[kk * 16 + jq];
        float4 w1 = sW[kk * 16 + jq + 1];
        u64 wp0 = pk2(w0.x, w0.y);
        u64 wp1 = pk2(w0.z, w0.w);
        u64 wp2 = pk2(w1.x, w1.y);
        u64 wp3 = pk2(w1.z, w1.w);
        float xv0 = sh[r0 + 0][kk];
        float xv1 = sh[r0 + 1][kk];
        float xv2 = sh[r0 + 2][kk];
        float xv3 = sh[r0 + 3][kk];
        u64 xd0 = pk2(xv0, xv0);
        u64 xd1 = pk2(xv1, xv1);
        u64 xd2 = pk2(xv2, xv2);
        u64 xd3 = pk2(xv3, xv3);
        fma2(acc[0][0], xd0, wp0); fma2(acc[0][1], xd0, wp1);
        fma2(acc[0][2], xd0, wp2); fma2(acc[0][3], xd0, wp3);
        fma2(acc[1][0], xd1, wp0); fma2(acc[1][1], xd1, wp1);
        fma2(acc[1][2], xd1, wp2); fma2(acc[1][3], xd1, wp3);
        fma2(acc[2][0], xd2, wp0); fma2(acc[2][1], xd2, wp1);
        fma2(acc[2][2], xd2, wp2); fma2(acc[2][3], xd2, wp3);
        fma2(acc[3][0], xd3, wp0); fma2(acc[3][1], xd3, wp1);
        fma2(acc[3][2], xd3, wp2); fma2(acc[3][3], xd3, wp3);
    }

#pragma unroll
    for (int rr = 0; rr < 4; rr++) {
        int grow = tile0 + r0 + rr;
        if (grow < N) {
            float2 a0 = upk(acc[rr][0]), a1 = upk(acc[rr][1]);
            float2 a2 = upk(acc[rr][2]), a3 = upk(acc[rr][3]);
            const float4* xr = reinterpret_cast<const float4*>(x + (size_t)grow * D + jq * 4);
            float4 x0 = xr[0], x1 = xr[1];
            float4* dst = reinterpret_cast<float4*>(out + (size_t)grow * D + jq * 4);
            dst[0] = make_float4(x0.x + a0.x, x0.y + a0.y, x0.z + a1.x, x0.w + a1.y);
            dst[1] = make_float4(x1.x + a2.x, x1.y + a2.y, x1.z + a3.x, x1.w + a3.y);
        }
    }
}

// ---------------------------------------------------------------------------
extern "C" void kernel_launch(void* const* d_in, const int* in_sizes, int n_in,
                              void* d_out, int out_size) {
    const float* x  = (const float*)d_in[0];
    const int*   ei = (const int*)d_in[1];
    const float* Wq = (const float*)d_in[2];
    const float* Wk = (const float*)d_in[3];
    const float* Wv = (const float*)d_in[4];
    const float* Wo = (const float*)d_in[5];
    float* out = (float*)d_out;

    int N = in_sizes[0] / D;
    int E = in_sizes[1] / 2;

    int tiles = (N + 63) / 64;

    zero_kernel<<<1184, 256>>>(N);
    qkv_kernel<<<tiles, 128>>>(x, Wq, Wk, Wv, N);
    int edge_threads = E * 8;
    edge_kernel<<<(edge_threads + 255) / 256, 256>>>(ei, E);
    out_kernel<<<tiles, 128>>>(x, Wo, out, N);
}

// round 4
// speedup vs baseline: 1.4573x; 1.1194x over previous
#include <cuda_runtime.h>
#include <cuda_fp16.h>
#include <cstdint>

#define D 64
#define NMAX 100000
#define EMAX 1600000
#define SCALE 0.125f  // D^-0.5 = 1/8

typedef unsigned long long u64;

// Scratch (device globals: allocation-free per harness rules)
__device__ __half g_Qh[NMAX * D];
__device__ __half g_Kh[NMAX * D];
__device__ __half g_Vh[NMAX * D];
__device__ float g_num[NMAX * D];
__device__ float g_denom[NMAX];

// ---- f32x2 packed-FMA helpers (sm_100+) -----------------------------------
__device__ __forceinline__ u64 pk2(float lo, float hi) {
    u64 r; asm("mov.b64 %0, {%1,%2};" : "=l"(r) : "f"(lo), "f"(hi)); return r;
}
__device__ __forceinline__ void fma2(u64& d, u64 a, u64 b) {
    asm("fma.rn.f32x2 %0, %1, %2, %0;" : "+l"(d) : "l"(a), "l"(b));
}
__device__ __forceinline__ float2 upk(u64 v) {
    float2 f; asm("mov.b64 {%0,%1}, %2;" : "=f"(f.x), "=f"(f.y) : "l"(v)); return f;
}

// ---------------------------------------------------------------------------
// Zero the accumulators (required every launch: graph replays).
// ---------------------------------------------------------------------------
__global__ void zero_kernel(int N) {
    const float4 z = make_float4(0.f, 0.f, 0.f, 0.f);
    int total4 = N * D / 4;
    for (int i = blockIdx.x * blockDim.x + threadIdx.x; i < total4;
         i += gridDim.x * blockDim.x) {
        reinterpret_cast<float4*>(g_num)[i] = z;
    }
    for (int i = blockIdx.x * blockDim.x + threadIdx.x; i < N;
         i += gridDim.x * blockDim.x) {
        g_denom[i] = 0.f;
    }
}

// ---------------------------------------------------------------------------
// Fused QKV projection (fp32 math, fp16 stores for the edge phase).
// 64-row tile, 128 threads; thread tile 4 rows x 8 cols as f32x2 pairs.
// ---------------------------------------------------------------------------
__global__ void __launch_bounds__(128) qkv_kernel(
    const float* __restrict__ x,
    const float* __restrict__ Wq,
    const float* __restrict__ Wk,
    const float* __restrict__ Wv, int N) {
    __shared__ float sx[64][65];
    __shared__ float4 sW[D * 16];

    const int tile0 = blockIdx.x * 64;

    for (int i = threadIdx.x; i < 64 * 16; i += 128) {
        int row = i >> 4;
        int c4 = i & 15;
        int grow = tile0 + row;
        float4 v = make_float4(0.f, 0.f, 0.f, 0.f);
        if (grow < N) v = reinterpret_cast<const float4*>(x + (size_t)grow * D)[c4];
        float* dst = &sx[row][c4 * 4];
        dst[0] = v.x; dst[1] = v.y; dst[2] = v.z; dst[3] = v.w;
    }

    const int jq = (threadIdx.x & 7) * 2;   // float4 index of first col group
    const int r0 = (threadIdx.x >> 3) * 4;  // first of 4 rows

    const float* Ws[3] = {Wq, Wk, Wv};
    __half* Gs[3] = {g_Qh, g_Kh, g_Vh};

#pragma unroll
    for (int p = 0; p < 3; p++) {
        __syncthreads();  // covers sx staging (p=0) / prior pass sW reads (p>0)
        for (int i = threadIdx.x; i < D * 16; i += 128)
            sW[i] = __ldg(reinterpret_cast<const float4*>(Ws[p]) + i);
        __syncthreads();

        u64 acc[4][4];
#pragma unroll
        for (int rr = 0; rr < 4; rr++)
#pragma unroll
            for (int cp = 0; cp < 4; cp++) acc[rr][cp] = 0ull;

#pragma unroll 8
        for (int kk = 0; kk < D; kk++) {
            float4 w0 = sW[kk * 16 + jq];
            float4 w1 = sW[kk * 16 + jq + 1];
            u64 wp0 = pk2(w0.x, w0.y);
            u64 wp1 = pk2(w0.z, w0.w);
            u64 wp2 = pk2(w1.x, w1.y);
            u64 wp3 = pk2(w1.z, w1.w);
            float xv0 = sx[r0 + 0][kk];
            float xv1 = sx[r0 + 1][kk];
            float xv2 = sx[r0 + 2][kk];
            float xv3 = sx[r0 + 3][kk];
            u64 xd0 = pk2(xv0, xv0);
            u64 xd1 = pk2(xv1, xv1);
            u64 xd2 = pk2(xv2, xv2);
            u64 xd3 = pk2(xv3, xv3);
            fma2(acc[0][0], xd0, wp0); fma2(acc[0][1], xd0, wp1);
            fma2(acc[0][2], xd0, wp2); fma2(acc[0][3], xd0, wp3);
            fma2(acc[1][0], xd1, wp0); fma2(acc[1][1], xd1, wp1);
            fma2(acc[1][2], xd1, wp2); fma2(acc[1][3], xd1, wp3);
            fma2(acc[2][0], xd2, wp0); fma2(acc[2][1], xd2, wp1);
            fma2(acc[2][2], xd2, wp2); fma2(acc[2][3], xd2, wp3);
            fma2(acc[3][0], xd3, wp0); fma2(acc[3][1], xd3, wp1);
            fma2(acc[3][2], xd3, wp2); fma2(acc[3][3], xd3, wp3);
        }

        __half* G = Gs[p];
#pragma unroll
        for (int rr = 0; rr < 4; rr++) {
            int grow = tile0 + r0 + rr;
            if (grow < N) {
                float2 a0 = upk(acc[rr][0]), a1 = upk(acc[rr][1]);
                float2 a2 = upk(acc[rr][2]), a3 = upk(acc[rr][3]);
                __half2 h0 = __float22half2_rn(a0);
                __half2 h1 = __float22half2_rn(a1);
                __half2 h2 = __float22half2_rn(a2);
                __half2 h3 = __float22half2_rn(a3);
                uint4 pkt;
                pkt.x = *reinterpret_cast<uint32_t*>(&h0);
                pkt.y = *reinterpret_cast<uint32_t*>(&h1);
                pkt.z = *reinterpret_cast<uint32_t*>(&h2);
                pkt.w = *reinterpret_cast<uint32_t*>(&h3);
                *reinterpret_cast<uint4*>(G + (size_t)grow * D + jq * 4) = pkt;
            }
        }
    }
}

// ---------------------------------------------------------------------------
// Edge pass: 8 threads per edge; Q/K/V gathered as fp16 (16B per thread each).
//   s = <Q[recv], K[send]> * SCALE ; p = exp(s)
//   denom[recv] += p ; num[recv] += p * V[send]   (fp32 vector red.global)
// No segment-max needed: logits are ~N(0,1); exp() is safe in fp32.
// ---------------------------------------------------------------------------
__global__ void edge_kernel(const int* __restrict__ ei, int E) {
    int idx = blockIdx.x * blockDim.x + threadIdx.x;
    int e = idx >> 3;
    int l = idx & 7;
    bool live = e < E;
    int ec = live ? e : 0;

    int snd = __ldg(&ei[ec]);       // edge_index[0] = sender
    int rcv = __ldg(&ei[E + ec]);   // edge_index[1] = receiver

    uint4 qu = reinterpret_cast<const uint4*>(g_Qh + (size_t)rcv * D)[l];
    uint4 ku = reinterpret_cast<const uint4*>(g_Kh + (size_t)snd * D)[l];

    float2 q0 = __half22float2(*reinterpret_cast<__half2*>(&qu.x));
    float2 q1 = __half22float2(*reinterpret_cast<__half2*>(&qu.y));
    float2 q2 = __half22float2(*reinterpret_cast<__half2*>(&qu.z));
    float2 q3 = __half22float2(*reinterpret_cast<__half2*>(&qu.w));
    float2 k0 = __half22float2(*reinterpret_cast<__half2*>(&ku.x));
    float2 k1 = __half22float2(*reinterpret_cast<__half2*>(&ku.y));
    float2 k2 = __half22float2(*reinterpret_cast<__half2*>(&ku.z));
    float2 k3 = __half22float2(*reinterpret_cast<__half2*>(&ku.w));

    float d = q0.x * k0.x + q0.y * k0.y + q1.x * k1.x + q1.y * k1.y
            + q2.x * k2.x + q2.y * k2.y + q3.x * k3.x + q3.y * k3.y;
    d += __shfl_xor_sync(0xffffffffu, d, 1);
    d += __shfl_xor_sync(0xffffffffu, d, 2);
    d += __shfl_xor_sync(0xffffffffu, d, 4);

    float p = __expf(d * SCALE);

    uint4 vu = reinterpret_cast<const uint4*>(g_Vh + (size_t)snd * D)[l];
    float2 v0 = __half22float2(*reinterpret_cast<__half2*>(&vu.x));
    float2 v1 = __half22float2(*reinterpret_cast<__half2*>(&vu.y));
    float2 v2 = __half22float2(*reinterpret_cast<__half2*>(&vu.z));
    float2 v3 = __half22float2(*reinterpret_cast<__half2*>(&vu.w));

    if (live) {
        if (l == 0) atomicAdd(&g_denom[rcv], p);
        float* dst = g_num + (size_t)rcv * D + l * 8;
        asm volatile("red.global.v4.f32.add [%0], {%1,%2,%3,%4};" ::"l"(dst),
                     "f"(p * v0.x), "f"(p * v0.y), "f"(p * v1.x), "f"(p * v1.y)
                     : "memory");
        asm volatile("red.global.v4.f32.add [%0], {%1,%2,%3,%4};" ::"l"(dst + 4),
                     "f"(p * v2.x), "f"(p * v2.y), "f"(p * v3.x), "f"(p * v3.y)
                     : "memory");
    }
}

// ---------------------------------------------------------------------------
// Output: out = x + (num/denom) @ Wo. f32x2 register-blocked, one pass.
// ---------------------------------------------------------------------------
__global__ void __launch_bounds__(128) out_kernel(
    const float* __restrict__ x,
    const float* __restrict__ Wo,
    float* __restrict__ out, int N) {
    __shared__ float sh[64][65];
    __shared__ float4 sW[D * 16];

    const int tile0 = blockIdx.x * 64;

    for (int i = threadIdx.x; i < 64 * 16; i += 128) {
        int row = i >> 4;
        int c4 = i & 15;
        int grow = tile0 + row;
        float4 v = make_float4(0.f, 0.f, 0.f, 0.f);
        if (grow < N) {
            float dn = g_denom[grow];
            float inv = dn > 0.f ? 1.0f / dn : 0.f;
            float4 nm = reinterpret_cast<const float4*>(g_num + (size_t)grow * D)[c4];
            v = make_float4(nm.x * inv, nm.y * inv, nm.z * inv, nm.w * inv);
        }
        float* dst = &sh[row][c4 * 4];
        dst[0] = v.x; dst[1] = v.y; dst[2] = v.z; dst[3] = v.w;
    }
    for (int i = threadIdx.x; i < D * 16; i += 128)
        sW[i] = __ldg(reinterpret_cast<const float4*>(Wo) + i);
    __syncthreads();

    const int jq = (threadIdx.x & 7) * 2;
    const int r0 = (threadIdx.x >> 3) * 4;

    u64 acc[4][4];
#pragma unroll
    for (int rr = 0; rr < 4; rr++)
#pragma unroll
        for (int cp = 0; cp < 4; cp++) acc[rr][cp] = 0ull;

#pragma unroll 8
    for (int kk = 0; kk < D; kk++) {
        float4 w0 = sW[kk * 16 + jq];
        float4 w1 = sW[kk * 16 + jq + 1];
        u64 wp0 = pk2(w0.x, w0.y);
        u64 wp1 = pk2(w0.z, w0.w);
        u64 wp2 = pk2(w1.x, w1.y);
        u64 wp3 = pk2(w1.z, w1.w);
        float xv0 = sh[r0 + 0][kk];
        float xv1 = sh[r0 + 1][kk];
        float xv2 = sh[r0 + 2][kk];
        float xv3 = sh[r0 + 3][kk];
        u64 xd0 = pk2(xv0, xv0);
        u64 xd1 = pk2(xv1, xv1);
        u64 xd2 = pk2(xv2, xv2);
        u64 xd3 = pk2(xv3, xv3);
        fma2(acc[0][0], xd0, wp0); fma2(acc[0][1], xd0, wp1);
        fma2(acc[0][2], xd0, wp2); fma2(acc[0][3], xd0, wp3);
        fma2(acc[1][0], xd1, wp0); fma2(acc[1][1], xd1, wp1);
        fma2(acc[1][2], xd1, wp2); fma2(acc[1][3], xd1, wp3);
        fma2(acc[2][0], xd2, wp0); fma2(acc[2][1], xd2, wp1);
        fma2(acc[2][2], xd2, wp2); fma2(acc[2][3], xd2, wp3);
        fma2(acc[3][0], xd3, wp0); fma2(acc[3][1], xd3, wp1);
        fma2(acc[3][2], xd3, wp2); fma2(acc[3][3], xd3, wp3);
    }

#pragma unroll
    for (int rr = 0; rr < 4; rr++) {
        int grow = tile0 + r0 + rr;
        if (grow < N) {
            float2 a0 = upk(acc[rr][0]), a1 = upk(acc[rr][1]);
            float2 a2 = upk(acc[rr][2]), a3 = upk(acc[rr][3]);
            const float4* xr = reinterpret_cast<const float4*>(x + (size_t)grow * D + jq * 4);
            float4 x0 = xr[0], x1 = xr[1];
            float4* dst = reinterpret_cast<float4*>(out + (size_t)grow * D + jq * 4);
            dst[0] = make_float4(x0.x + a0.x, x0.y + a0.y, x0.z + a1.x, x0.w + a1.y);
            dst[1] = make_float4(x1.x + a2.x, x1.y + a2.y, x1.z + a3.x, x1.w + a3.y);
        }
    }
}

// ---------------------------------------------------------------------------
extern "C" void kernel_launch(void* const* d_in, const int* in_sizes, int n_in,
                              void* d_out, int out_size) {
    const float* x  = (const float*)d_in[0];
    const int*   ei = (const int*)d_in[1];
    const float* Wq = (const float*)d_in[2];
    const float* Wk = (const float*)d_in[3];
    const float* Wv = (const float*)d_in[4];
    const float* Wo = (const float*)d_in[5];
    float* out = (float*)d_out;

    int N = in_sizes[0] / D;
    int E = in_sizes[1] / 2;

    int tiles = (N + 63) / 64;

    zero_kernel<<<1184, 256>>>(N);
    qkv_kernel<<<tiles, 128>>>(x, Wq, Wk, Wv, N);
    int edge_threads = E * 8;
    edge_kernel<<<(edge_threads + 255) / 256, 256>>>(ei, E);
    out_kernel<<<tiles, 128>>>(x, Wo, out, N);
}

// round 5
// speedup vs baseline: 2.0234x; 1.3885x over previous
#include <cuda_runtime.h>
#include <cuda_fp16.h>
#include <cstdint>

#define D 64
#define NMAX 100000
#define EMAX 1600000
#define SCALE 0.125f  // D^-0.5 = 1/8

// Scratch (device globals: allocation-free per harness rules)
__device__ __half g_Qh[NMAX * D];
__device__ __half g_Kh[NMAX * D];
__device__ __half g_Vh[NMAX * D];
__device__ float g_num[NMAX * D];
__device__ float g_denom[NMAX];

__device__ __forceinline__ uint32_t smem_u32(const void* p) {
    uint32_t a;
    asm("{ .reg .u64 t; cvta.to.shared.u64 t, %1; cvt.u32.u64 %0, t; }"
        : "=r"(a) : "l"(p));
    return a;
}

__device__ __forceinline__ void ldsm_x4(uint32_t& r0, uint32_t& r1,
                                        uint32_t& r2, uint32_t& r3,
                                        uint32_t addr) {
    asm volatile("ldmatrix.sync.aligned.m8n8.x4.shared.b16 {%0,%1,%2,%3}, [%4];"
                 : "=r"(r0), "=r"(r1), "=r"(r2), "=r"(r3) : "r"(addr));
}
__device__ __forceinline__ void ldsm_x2(uint32_t& r0, uint32_t& r1,
                                        uint32_t addr) {
    asm volatile("ldmatrix.sync.aligned.m8n8.x2.shared.b16 {%0,%1}, [%2];"
                 : "=r"(r0), "=r"(r1) : "r"(addr));
}
__device__ __forceinline__ void mma_16816(float* c, uint32_t a0, uint32_t a1,
                                          uint32_t a2, uint32_t a3,
                                          uint32_t b0, uint32_t b1) {
    asm volatile(
        "mma.sync.aligned.m16n8k16.row.col.f32.f16.f16.f32 "
        "{%0,%1,%2,%3}, {%4,%5,%6,%7}, {%8,%9}, {%0,%1,%2,%3};"
        : "+f"(c[0]), "+f"(c[1]), "+f"(c[2]), "+f"(c[3])
        : "r"(a0), "r"(a1), "r"(a2), "r"(a3), "r"(b0), "r"(b1));
}

// smem pitches (halves). 72*2=144B row stride: 8 consecutive rows land in
// distinct 16B bank groups -> conflict-free ldmatrix.
#define PA 72

// ---------------------------------------------------------------------------
// Zero the accumulators (required every launch: graph replays).
// ---------------------------------------------------------------------------
__global__ void zero_kernel(int N) {
    const float4 z = make_float4(0.f, 0.f, 0.f, 0.f);
    int total4 = N * D / 4;
    for (int i = blockIdx.x * blockDim.x + threadIdx.x; i < total4;
         i += gridDim.x * blockDim.x) {
        reinterpret_cast<float4*>(g_num)[i] = z;
    }
    for (int i = blockIdx.x * blockDim.x + threadIdx.x; i < N;
         i += gridDim.x * blockDim.x) {
        g_denom[i] = 0.f;
    }
}

// ---------------------------------------------------------------------------
// Fused QKV projection via HMMA. 128-row tile, 256 threads (8 warps).
// A = x tile (fp16, row-major, pitch 72). B = W^T staged [n][k] so both
// operands use non-trans ldmatrix. fp32 accum; fp16 stores.
// ---------------------------------------------------------------------------
__global__ void __launch_bounds__(256) qkv_kernel(
    const float* __restrict__ x,
    const float* __restrict__ Wq,
    const float* __restrict__ Wk,
    const float* __restrict__ Wv, int N) {
    __shared__ __half sA[128 * PA];
    __shared__ __half sW[64 * PA];  // W^T: sW[n][k]

    const int tid = threadIdx.x;
    const int lane = tid & 31;
    const int warp = tid >> 5;
    const int tile0 = blockIdx.x * 128;

    // Stage x tile as fp16 (zero-pad past N).
    for (int i = tid; i < 128 * 16; i += 256) {
        int row = i >> 4;
        int c4 = i & 15;
        int grow = tile0 + row;
        float4 v = make_float4(0.f, 0.f, 0.f, 0.f);
        if (grow < N) v = reinterpret_cast<const float4*>(x + (size_t)grow * D)[c4];
        __half2 h0 = __floats2half2_rn(v.x, v.y);
        __half2 h1 = __floats2half2_rn(v.z, v.w);
        uint2 pkt = make_uint2(*reinterpret_cast<uint32_t*>(&h0),
                               *reinterpret_cast<uint32_t*>(&h1));
        *reinterpret_cast<uint2*>(&sA[row * PA + c4 * 4]) = pkt;
    }

    const uint32_t sA_u = smem_u32(sA);
    const uint32_t sW_u = smem_u32(sW);

    // ldmatrix lane addressing (non-trans):
    // A x4: mats 0..3 = (rows 0-7,k0) (rows 8-15,k0) (rows 0-7,k0+8) (rows 8-15,k0+8)
    const int mrow = warp * 16 + (lane & 7) + ((lane >> 3) & 1) * 8;
    const int acol = (lane >> 4) * 8;
    const uint32_t aBase = sA_u + (mrow * PA + acol) * 2;
    // B x2 (lanes 0-15): mats 0..1 = (n-rows 0-7, k0) (n-rows 0-7, k0+8)
    const int l15 = lane & 15;
    const int nrow_l = l15 & 7;
    const int bcol = ((l15 >> 3) & 1) * 8;

    const int gid = lane >> 2;   // output row within m16 (and +8)
    const int tig = lane & 3;    // output col pair

    const float* Ws[3] = {Wq, Wk, Wv};
    __half* Gs[3] = {g_Qh, g_Kh, g_Vh};

#pragma unroll
    for (int p = 0; p < 3; p++) {
        __syncthreads();  // covers sA staging (p=0) / previous-pass sW reads
        // Stage W^T: sW[n][k] = W[k][n]
        for (int i = tid; i < 64 * 16; i += 256) {
            int k = i >> 4;
            int c4 = i & 15;
            float4 w = __ldg(reinterpret_cast<const float4*>(Ws[p] + k * D + c4 * 4));
            sW[(c4 * 4 + 0) * PA + k] = __float2half_rn(w.x);
            sW[(c4 * 4 + 1) * PA + k] = __float2half_rn(w.y);
            sW[(c4 * 4 + 2) * PA + k] = __float2half_rn(w.z);
            sW[(c4 * 4 + 3) * PA + k] = __float2half_rn(w.w);
        }
        __syncthreads();

        float acc[8][4];
#pragma unroll
        for (int nt = 0; nt < 8; nt++)
#pragma unroll
            for (int q = 0; q < 4; q++) acc[nt][q] = 0.f;

#pragma unroll
        for (int k = 0; k < 4; k++) {
            uint32_t a0, a1, a2, a3;
            ldsm_x4(a0, a1, a2, a3, aBase + k * 32);
#pragma unroll
            for (int nt = 0; nt < 8; nt++) {
                uint32_t b0, b1;
                ldsm_x2(b0, b1,
                        sW_u + ((nt * 8 + nrow_l) * PA + k * 16 + bcol) * 2);
                mma_16816(acc[nt], a0, a1, a2, a3, b0, b1);
            }
        }

        __half* G = Gs[p];
        int r_lo = tile0 + warp * 16 + gid;
        int r_hi = r_lo + 8;
#pragma unroll
        for (int nt = 0; nt < 8; nt++) {
            int col = nt * 8 + tig * 2;
            if (r_lo < N)
                *reinterpret_cast<__half2*>(G + (size_t)r_lo * D + col) =
                    __floats2half2_rn(acc[nt][0], acc[nt][1]);
            if (r_hi < N)
                *reinterpret_cast<__half2*>(G + (size_t)r_hi * D + col) =
                    __floats2half2_rn(acc[nt][2], acc[nt][3]);
        }
    }
}

// ---------------------------------------------------------------------------
// Edge pass: 8 threads per edge; fp16 gathers, fp32 vector red scatter.
// ---------------------------------------------------------------------------
__global__ void edge_kernel(const int* __restrict__ ei, int E) {
    int idx = blockIdx.x * blockDim.x + threadIdx.x;
    int e = idx >> 3;
    int l = idx & 7;
    bool live = e < E;
    int ec = live ? e : 0;

    int snd = __ldg(&ei[ec]);       // edge_index[0] = sender
    int rcv = __ldg(&ei[E + ec]);   // edge_index[1] = receiver

    uint4 qu = reinterpret_cast<const uint4*>(g_Qh + (size_t)rcv * D)[l];
    uint4 ku = reinterpret_cast<const uint4*>(g_Kh + (size_t)snd * D)[l];

    float2 q0 = __half22float2(*reinterpret_cast<__half2*>(&qu.x));
    float2 q1 = __half22float2(*reinterpret_cast<__half2*>(&qu.y));
    float2 q2 = __half22float2(*reinterpret_cast<__half2*>(&qu.z));
    float2 q3 = __half22float2(*reinterpret_cast<__half2*>(&qu.w));
    float2 k0 = __half22float2(*reinterpret_cast<__half2*>(&ku.x));
    float2 k1 = __half22float2(*reinterpret_cast<__half2*>(&ku.y));
    float2 k2 = __half22float2(*reinterpret_cast<__half2*>(&ku.z));
    float2 k3 = __half22float2(*reinterpret_cast<__half2*>(&ku.w));

    float d = q0.x * k0.x + q0.y * k0.y + q1.x * k1.x + q1.y * k1.y
            + q2.x * k2.x + q2.y * k2.y + q3.x * k3.x + q3.y * k3.y;
    d += __shfl_xor_sync(0xffffffffu, d, 1);
    d += __shfl_xor_sync(0xffffffffu, d, 2);
    d += __shfl_xor_sync(0xffffffffu, d, 4);

    float p = __expf(d * SCALE);

    uint4 vu = reinterpret_cast<const uint4*>(g_Vh + (size_t)snd * D)[l];
    float2 v0 = __half22float2(*reinterpret_cast<__half2*>(&vu.x));
    float2 v1 = __half22float2(*reinterpret_cast<__half2*>(&vu.y));
    float2 v2 = __half22float2(*reinterpret_cast<__half2*>(&vu.z));
    float2 v3 = __half22float2(*reinterpret_cast<__half2*>(&vu.w));

    if (live) {
        if (l == 0) atomicAdd(&g_denom[rcv], p);
        float* dst = g_num + (size_t)rcv * D + l * 8;
        asm volatile("red.global.v4.f32.add [%0], {%1,%2,%3,%4};" ::"l"(dst),
                     "f"(p * v0.x), "f"(p * v0.y), "f"(p * v1.x), "f"(p * v1.y)
                     : "memory");
        asm volatile("red.global.v4.f32.add [%0], {%1,%2,%3,%4};" ::"l"(dst + 4),
                     "f"(p * v2.x), "f"(p * v2.y), "f"(p * v3.x), "f"(p * v3.y)
                     : "memory");
    }
}

// ---------------------------------------------------------------------------
// Output: out = x + (num/denom) @ Wo via HMMA (h in fp16, residual fp32).
// ---------------------------------------------------------------------------
__global__ void __launch_bounds__(256) out_kernel(
    const float* __restrict__ x,
    const float* __restrict__ Wo,
    float* __restrict__ out, int N) {
    __shared__ __half sA[128 * PA];
    __shared__ __half sW[64 * PA];

    const int tid = threadIdx.x;
    const int lane = tid & 31;
    const int warp = tid >> 5;
    const int tile0 = blockIdx.x * 128;

    // Stage h = num/denom as fp16.
    for (int i = tid; i < 128 * 16; i += 256) {
        int row = i >> 4;
        int c4 = i & 15;
        int grow = tile0 + row;
        float4 v = make_float4(0.f, 0.f, 0.f, 0.f);
        if (grow < N) {
            float dn = g_denom[grow];
            float inv = dn > 0.f ? 1.0f / dn : 0.f;
            float4 nm = reinterpret_cast<const float4*>(g_num + (size_t)grow * D)[c4];
            v = make_float4(nm.x * inv, nm.y * inv, nm.z * inv, nm.w * inv);
        }
        __half2 h0 = __floats2half2_rn(v.x, v.y);
        __half2 h1 = __floats2half2_rn(v.z, v.w);
        uint2 pkt = make_uint2(*reinterpret_cast<uint32_t*>(&h0),
                               *reinterpret_cast<uint32_t*>(&h1));
        *reinterpret_cast<uint2*>(&sA[row * PA + c4 * 4]) = pkt;
    }
    // Stage Wo^T.
    for (int i = tid; i < 64 * 16; i += 256) {
        int k = i >> 4;
        int c4 = i & 15;
        float4 w = __ldg(reinterpret_cast<const float4*>(Wo + k * D + c4 * 4));
        sW[(c4 * 4 + 0) * PA + k] = __float2half_rn(w.x);
        sW[(c4 * 4 + 1) * PA + k] = __float2half_rn(w.y);
        sW[(c4 * 4 + 2) * PA + k] = __float2half_rn(w.z);
        sW[(c4 * 4 + 3) * PA + k] = __float2half_rn(w.w);
    }
    __syncthreads();

    const uint32_t sA_u = smem_u32(sA);
    const uint32_t sW_u = smem_u32(sW);

    const int mrow = warp * 16 + (lane & 7) + ((lane >> 3) & 1) * 8;
    const int acol = (lane >> 4) * 8;
    const uint32_t aBase = sA_u + (mrow * PA + acol) * 2;
    const int l15 = lane & 15;
    const int nrow_l = l15 & 7;
    const int bcol = ((l15 >> 3) & 1) * 8;

    float acc[8][4];
#pragma unroll
    for (int nt = 0; nt < 8; nt++)
#pragma unroll
        for (int q = 0; q < 4; q++) acc[nt][q] = 0.f;

#pragma unroll
    for (int k = 0; k < 4; k++) {
        uint32_t a0, a1, a2, a3;
        ldsm_x4(a0, a1, a2, a3, aBase + k * 32);
#pragma unroll
        for (int nt = 0; nt < 8; nt++) {
            uint32_t b0, b1;
            ldsm_x2(b0, b1, sW_u + ((nt * 8 + nrow_l) * PA + k * 16 + bcol) * 2);
            mma_16816(acc[nt], a0, a1, a2, a3, b0, b1);
        }
    }

    const int gid = lane >> 2;
    const int tig = lane & 3;
    int r_lo = tile0 + warp * 16 + gid;
    int r_hi = r_lo + 8;
#pragma unroll
    for (int nt = 0; nt < 8; nt++) {
        int col = nt * 8 + tig * 2;
        if (r_lo < N) {
            float2 xr = *reinterpret_cast<const float2*>(x + (size_t)r_lo * D + col);
            *reinterpret_cast<float2*>(out + (size_t)r_lo * D + col) =
                make_float2(xr.x + acc[nt][0], xr.y + acc[nt][1]);
        }
        if (r_hi < N) {
            float2 xr = *reinterpret_cast<const float2*>(x + (size_t)r_hi * D + col);
            *reinterpret_cast<float2*>(out + (size_t)r_hi * D + col) =
                make_float2(xr.x + acc[nt][2], xr.y + acc[nt][3]);
        }
    }
}

// ---------------------------------------------------------------------------
extern "C" void kernel_launch(void* const* d_in, const int* in_sizes, int n_in,
                              void* d_out, int out_size) {
    const float* x  = (const float*)d_in[0];
    const int*   ei = (const int*)d_in[1];
    const float* Wq = (const float*)d_in[2];
    const float* Wk = (const float*)d_in[3];
    const float* Wv = (const float*)d_in[4];
    const float* Wo = (const float*)d_in[5];
    float* out = (float*)d_out;

    int N = in_sizes[0] / D;
    int E = in_sizes[1] / 2;

    int tiles = (N + 127) / 128;

    zero_kernel<<<1184, 256>>>(N);
    qkv_kernel<<<tiles, 256>>>(x, Wq, Wk, Wv, N);
    int edge_threads = E * 8;
    edge_kernel<<<(edge_threads + 255) / 256, 256>>>(ei, E);
    out_kernel<<<tiles, 256>>>(x, Wo, out, N);
}

// round 6
// speedup vs baseline: 2.2951x; 1.1343x over previous
#include <cuda_runtime.h>
#include <cuda_fp16.h>
#include <cstdint>

#define D 64
#define NMAX 100000
#define EMAX 1600000
#define SCALE 0.125f  // D^-0.5 = 1/8

// Scratch (device globals: allocation-free per harness rules)
__device__ __half g_Qh[NMAX * D];
__device__ __half g_Kh[NMAX * D];
__device__ __half g_Vh[NMAX * D];
__device__ __half g_Hh[NMAX * D];     // h = softmax-aggregated V (normalized)
__device__ int g_cnt[NMAX];
__device__ int g_offs[NMAX + 1];
__device__ int g_cursor[NMAX];
__device__ int g_ssend[EMAX];
__device__ int g_partial[128];

__device__ __forceinline__ uint32_t smem_u32(const void* p) {
    uint32_t a;
    asm("{ .reg .u64 t; cvta.to.shared.u64 t, %1; cvt.u32.u64 %0, t; }"
        : "=r"(a) : "l"(p));
    return a;
}
__device__ __forceinline__ void ldsm_x4(uint32_t& r0, uint32_t& r1,
                                        uint32_t& r2, uint32_t& r3,
                                        uint32_t addr) {
    asm volatile("ldmatrix.sync.aligned.m8n8.x4.shared.b16 {%0,%1,%2,%3}, [%4];"
                 : "=r"(r0), "=r"(r1), "=r"(r2), "=r"(r3) : "r"(addr));
}
__device__ __forceinline__ void ldsm_x2(uint32_t& r0, uint32_t& r1,
                                        uint32_t addr) {
    asm volatile("ldmatrix.sync.aligned.m8n8.x2.shared.b16 {%0,%1}, [%2];"
                 : "=r"(r0), "=r"(r1) : "r"(addr));
}
__device__ __forceinline__ void mma_16816(float* c, uint32_t a0, uint32_t a1,
                                          uint32_t a2, uint32_t a3,
                                          uint32_t b0, uint32_t b1) {
    asm volatile(
        "mma.sync.aligned.m16n8k16.row.col.f32.f16.f16.f32 "
        "{%0,%1,%2,%3}, {%4,%5,%6,%7}, {%8,%9}, {%0,%1,%2,%3};"
        : "+f"(c[0]), "+f"(c[1]), "+f"(c[2]), "+f"(c[3])
        : "r"(a0), "r"(a1), "r"(a2), "r"(a3), "r"(b0), "r"(b1));
}

#define PA 72  // smem pitch in halves: 144B row stride, conflict-free ldmatrix

// ---------------------------------------------------------------------------
// CSR construction (recomputed every launch; graph-replay safe).
// ---------------------------------------------------------------------------
__global__ void zero_cnt_kernel(int N) {
    int i = blockIdx.x * blockDim.x + threadIdx.x;
    if (i < N) g_cnt[i] = 0;
}

__global__ void hist_kernel(const int* __restrict__ ei, int E) {
    int i = blockIdx.x * blockDim.x + threadIdx.x;
    if (i < E) atomicAdd(&g_cnt[__ldg(&ei[E + i])], 1);
}

__global__ void scan_blocks_kernel(int N) {
    __shared__ int s[1024];
    int i = blockIdx.x * 1024 + threadIdx.x;
    int v = (i < N) ? g_cnt[i] : 0;
    s[threadIdx.x] = v;
    __syncthreads();
    for (int off = 1; off < 1024; off <<= 1) {
        int t = (threadIdx.x >= (unsigned)off) ? s[threadIdx.x - off] : 0;
        __syncthreads();
        s[threadIdx.x] += t;
        __syncthreads();
    }
    if (i < N) g_offs[i] = s[threadIdx.x] - v;  // block-local exclusive
    if (threadIdx.x == 1023) g_partial[blockIdx.x] = s[1023];
}

__global__ void scan_partials_kernel(int nb) {  // nb <= 128
    __shared__ int s[128];
    int v = (threadIdx.x < (unsigned)nb) ? g_partial[threadIdx.x] : 0;
    s[threadIdx.x] = v;
    __syncthreads();
    for (int off = 1; off < 128; off <<= 1) {
        int t = (threadIdx.x >= (unsigned)off) ? s[threadIdx.x - off] : 0;
        __syncthreads();
        s[threadIdx.x] += t;
        __syncthreads();
    }
    if (threadIdx.x < (unsigned)nb) g_partial[threadIdx.x] = s[threadIdx.x] - v;
}

__global__ void add_offsets_kernel(int N, int E) {
    int i = blockIdx.x * blockDim.x + threadIdx.x;
    if (i < N) {
        int o = g_offs[i] + g_partial[i >> 10];
        g_offs[i] = o;
        g_cursor[i] = o;
    }
    if (i == 0) g_offs[N] = E;
}

__global__ void scatter_kernel(const int* __restrict__ ei, int E) {
    int i = blockIdx.x * blockDim.x + threadIdx.x;
    if (i < E) {
        int snd = __ldg(&ei[i]);
        int rcv = __ldg(&ei[E + i]);
        int pos = atomicAdd(&g_cursor[rcv], 1);
        g_ssend[pos] = snd;
    }
}

// ---------------------------------------------------------------------------
// Fused QKV projection via HMMA (fp32 accum, fp16 stores). Unchanged from R5.
// ---------------------------------------------------------------------------
__global__ void __launch_bounds__(256) qkv_kernel(
    const float* __restrict__ x,
    const float* __restrict__ Wq,
    const float* __restrict__ Wk,
    const float* __restrict__ Wv, int N) {
    __shared__ __half sA[128 * PA];
    __shared__ __half sW[64 * PA];  // W^T: sW[n][k]

    const int tid = threadIdx.x;
    const int lane = tid & 31;
    const int warp = tid >> 5;
    const int tile0 = blockIdx.x * 128;

    for (int i = tid; i < 128 * 16; i += 256) {
        int row = i >> 4;
        int c4 = i & 15;
        int grow = tile0 + row;
        float4 v = make_float4(0.f, 0.f, 0.f, 0.f);
        if (grow < N) v = reinterpret_cast<const float4*>(x + (size_t)grow * D)[c4];
        __half2 h0 = __floats2half2_rn(v.x, v.y);
        __half2 h1 = __floats2half2_rn(v.z, v.w);
        uint2 pkt = make_uint2(*reinterpret_cast<uint32_t*>(&h0),
                               *reinterpret_cast<uint32_t*>(&h1));
        *reinterpret_cast<uint2*>(&sA[row * PA + c4 * 4]) = pkt;
    }

    const uint32_t sA_u = smem_u32(sA);
    const uint32_t sW_u = smem_u32(sW);

    const int mrow = warp * 16 + (lane & 7) + ((lane >> 3) & 1) * 8;
    const int acol = (lane >> 4) * 8;
    const uint32_t aBase = sA_u + (mrow * PA + acol) * 2;
    const int l15 = lane & 15;
    const int nrow_l = l15 & 7;
    const int bcol = ((l15 >> 3) & 1) * 8;

    const int gid = lane >> 2;
    const int tig = lane & 3;

    const float* Ws[3] = {Wq, Wk, Wv};
    __half* Gs[3] = {g_Qh, g_Kh, g_Vh};

#pragma unroll
    for (int p = 0; p < 3; p++) {
        __syncthreads();
        for (int i = tid; i < 64 * 16; i += 256) {
            int k = i >> 4;
            int c4 = i & 15;
            float4 w = __ldg(reinterpret_cast<const float4*>(Ws[p] + k * D + c4 * 4));
            sW[(c4 * 4 + 0) * PA + k] = __float2half_rn(w.x);
            sW[(c4 * 4 + 1) * PA + k] = __float2half_rn(w.y);
            sW[(c4 * 4 + 2) * PA + k] = __float2half_rn(w.z);
            sW[(c4 * 4 + 3) * PA + k] = __float2half_rn(w.w);
        }
        __syncthreads();

        float acc[8][4];
#pragma unroll
        for (int nt = 0; nt < 8; nt++)
#pragma unroll
            for (int q = 0; q < 4; q++) acc[nt][q] = 0.f;

#pragma unroll
        for (int k = 0; k < 4; k++) {
            uint32_t a0, a1, a2, a3;
            ldsm_x4(a0, a1, a2, a3, aBase + k * 32);
#pragma unroll
            for (int nt = 0; nt < 8; nt++) {
                uint32_t b0, b1;
                ldsm_x2(b0, b1,
                        sW_u + ((nt * 8 + nrow_l) * PA + k * 16 + bcol) * 2);
                mma_16816(acc[nt], a0, a1, a2, a3, b0, b1);
            }
        }

        __half* G = Gs[p];
        int r_lo = tile0 + warp * 16 + gid;
        int r_hi = r_lo + 8;
#pragma unroll
        for (int nt = 0; nt < 8; nt++) {
            int col = nt * 8 + tig * 2;
            if (r_lo < N)
                *reinterpret_cast<__half2*>(G + (size_t)r_lo * D + col) =
                    __floats2half2_rn(acc[nt][0], acc[nt][1]);
            if (r_hi < N)
                *reinterpret_cast<__half2*>(G + (size_t)r_hi * D + col) =
                    __floats2half2_rn(acc[nt][2], acc[nt][3]);
        }
    }
}

// ---------------------------------------------------------------------------
// CSR aggregation: one warp per receiver. Q row register-resident (2 floats
// per lane); per edge: K row (4B/lane), dot + 5-shfl reduce, exp, V row,
// fp32 register accumulate. One fp16 h-row write per receiver. No atomics.
// ---------------------------------------------------------------------------
__global__ void __launch_bounds__(256) aggregate_kernel(int N) {
    int wg = (blockIdx.x * blockDim.x + threadIdx.x) >> 5;
    int lane = threadIdx.x & 31;
    if (wg >= N) return;
    int rcv = wg;
    int start = g_offs[rcv];
    int end = g_offs[rcv + 1];

    float2 q = __half22float2(
        reinterpret_cast<const __half2*>(g_Qh + (size_t)rcv * D)[lane]);

    float2 acc = make_float2(0.f, 0.f);
    float denom = 0.f;

    for (int base = start; base < end; base += 32) {
        int cnt = min(32, end - base);
        int sreg = (base + lane < end) ? g_ssend[base + lane] : 0;
        for (int j = 0; j < cnt; j++) {
            int snd = __shfl_sync(0xffffffffu, sreg, j);
            float2 k = __half22float2(
                reinterpret_cast<const __half2*>(g_Kh + (size_t)snd * D)[lane]);
            float2 v = __half22float2(
                reinterpret_cast<const __half2*>(g_Vh + (size_t)snd * D)[lane]);
            float part = q.x * k.x + q.y * k.y;
            part += __shfl_xor_sync(0xffffffffu, part, 1);
            part += __shfl_xor_sync(0xffffffffu, part, 2);
            part += __shfl_xor_sync(0xffffffffu, part, 4);
            part += __shfl_xor_sync(0xffffffffu, part, 8);
            part += __shfl_xor_sync(0xffffffffu, part, 16);
            float p = __expf(part * SCALE);
            acc.x = fmaf(p, v.x, acc.x);
            acc.y = fmaf(p, v.y, acc.y);
            denom += p;
        }
    }

    float inv = denom > 0.f ? 1.0f / denom : 0.f;
    reinterpret_cast<__half2*>(g_Hh + (size_t)rcv * D)[lane] =
        __floats2half2_rn(acc.x * inv, acc.y * inv);
}

// ---------------------------------------------------------------------------
// Output: out = x + h @ Wo via HMMA (h already fp16+normalized in g_Hh).
// ---------------------------------------------------------------------------
__global__ void __launch_bounds__(256) out_kernel(
    const float* __restrict__ x,
    const float* __restrict__ Wo,
    float* __restrict__ out, int N) {
    __shared__ __half sA[128 * PA];
    __shared__ __half sW[64 * PA];

    const int tid = threadIdx.x;
    const int lane = tid & 31;
    const int warp = tid >> 5;
    const int tile0 = blockIdx.x * 128;

    // Stage h tile directly (already fp16). 8 halves (16B) per chunk.
    for (int i = tid; i < 128 * 8; i += 256) {
        int row = i >> 3;
        int c8 = i & 7;
        int grow = tile0 + row;
        uint4 pkt = make_uint4(0u, 0u, 0u, 0u);
        if (grow < N)
            pkt = reinterpret_cast<const uint4*>(g_Hh + (size_t)grow * D)[c8];
        *reinterpret_cast<uint4*>(&sA[row * PA + c8 * 8]) = pkt;
    }
    for (int i = tid; i < 64 * 16; i += 256) {
        int k = i >> 4;
        int c4 = i & 15;
        float4 w = __ldg(reinterpret_cast<const float4*>(Wo + k * D + c4 * 4));
        sW[(c4 * 4 + 0) * PA + k] = __float2half_rn(w.x);
        sW[(c4 * 4 + 1) * PA + k] = __float2half_rn(w.y);
        sW[(c4 * 4 + 2) * PA + k] = __float2half_rn(w.z);
        sW[(c4 * 4 + 3) * PA + k] = __float2half_rn(w.w);
    }
    __syncthreads();

    const uint32_t sA_u = smem_u32(sA);
    const uint32_t sW_u = smem_u32(sW);

    const int mrow = warp * 16 + (lane & 7) + ((lane >> 3) & 1) * 8;
    const int acol = (lane >> 4) * 8;
    const uint32_t aBase = sA_u + (mrow * PA + acol) * 2;
    const int l15 = lane & 15;
    const int nrow_l = l15 & 7;
    const int bcol = ((l15 >> 3) & 1) * 8;

    float acc[8][4];
#pragma unroll
    for (int nt = 0; nt < 8; nt++)
#pragma unroll
        for (int q = 0; q < 4; q++) acc[nt][q] = 0.f;

#pragma unroll
    for (int k = 0; k < 4; k++) {
        uint32_t a0, a1, a2, a3;
        ldsm_x4(a0, a1, a2, a3, aBase + k * 32);
#pragma unroll
        for (int nt = 0; nt < 8; nt++) {
            uint32_t b0, b1;
            ldsm_x2(b0, b1, sW_u + ((nt * 8 + nrow_l) * PA + k * 16 + bcol) * 2);
            mma_16816(acc[nt], a0, a1, a2, a3, b0, b1);
        }
    }

    const int gid = lane >> 2;
    const int tig = lane & 3;
    int r_lo = tile0 + warp * 16 + gid;
    int r_hi = r_lo + 8;
#pragma unroll
    for (int nt = 0; nt < 8; nt++) {
        int col = nt * 8 + tig * 2;
        if (r_lo < N) {
            float2 xr = *reinterpret_cast<const float2*>(x + (size_t)r_lo * D + col);
            *reinterpret_cast<float2*>(out + (size_t)r_lo * D + col) =
                make_float2(xr.x + acc[nt][0], xr.y + acc[nt][1]);
        }
        if (r_hi < N) {
            float2 xr = *reinterpret_cast<const float2*>(x + (size_t)r_hi * D + col);
            *reinterpret_cast<float2*>(out + (size_t)r_hi * D + col) =
                make_float2(xr.x + acc[nt][2], xr.y + acc[nt][3]);
        }
    }
}

// ---------------------------------------------------------------------------
extern "C" void kernel_launch(void* const* d_in, const int* in_sizes, int n_in,
                              void* d_out, int out_size) {
    const float* x  = (const float*)d_in[0];
    const int*   ei = (const int*)d_in[1];
    const float* Wq = (const float*)d_in[2];
    const float* Wk = (const float*)d_in[3];
    const float* Wv = (const float*)d_in[4];
    const float* Wo = (const float*)d_in[5];
    float* out = (float*)d_out;

    int N = in_sizes[0] / D;
    int E = in_sizes[1] / 2;

    int tiles = (N + 127) / 128;
    int nblk = (N + 1023) / 1024;

    // CSR build (independent of projections, runs first on the stream)
    zero_cnt_kernel<<<(N + 255) / 256, 256>>>(N);
    hist_kernel<<<(E + 255) / 256, 256>>>(ei, E);
    scan_blocks_kernel<<<nblk, 1024>>>(N);
    scan_partials_kernel<<<1, 128>>>(nblk);
    add_offsets_kernel<<<(N + 255) / 256, 256>>>(N, E);
    scatter_kernel<<<(E + 255) / 256, 256>>>(ei, E);

    // Projections + aggregation + output
    qkv_kernel<<<tiles, 256>>>(x, Wq, Wk, Wv, N);
    aggregate_kernel<<<(N * 32 + 255) / 256, 256>>>(N);
    out_kernel<<<tiles, 256>>>(x, Wo, out, N);
}

// round 7
// speedup vs baseline: 2.4495x; 1.0672x over previous
#include <cuda_runtime.h>
#include <cuda_fp16.h>
#include <cstdint>

#define D 64
#define NMAX 100000
#define EMAX 1600000
#define SCALE 0.125f  // D^-0.5 = 1/8

// Scratch (device globals: allocation-free per harness rules)
__device__ __half g_Qh[NMAX * D];
__device__ __half g_Kh[NMAX * D];
__device__ __half g_Vh[NMAX * D];
__device__ __half g_Hh[NMAX * D];     // h = softmax-aggregated V (normalized)
__device__ int g_cnt[NMAX];
__device__ int g_offs[NMAX];
__device__ int g_cursor[NMAX];
__device__ int g_ssend[EMAX];
__device__ int g_total;

__device__ __forceinline__ uint32_t smem_u32(const void* p) {
    uint32_t a;
    asm("{ .reg .u64 t; cvta.to.shared.u64 t, %1; cvt.u32.u64 %0, t; }"
        : "=r"(a) : "l"(p));
    return a;
}
__device__ __forceinline__ void ldsm_x4(uint32_t& r0, uint32_t& r1,
                                        uint32_t& r2, uint32_t& r3,
                                        uint32_t addr) {
    asm volatile("ldmatrix.sync.aligned.m8n8.x4.shared.b16 {%0,%1,%2,%3}, [%4];"
                 : "=r"(r0), "=r"(r1), "=r"(r2), "=r"(r3) : "r"(addr));
}
__device__ __forceinline__ void ldsm_x2(uint32_t& r0, uint32_t& r1,
                                        uint32_t addr) {
    asm volatile("ldmatrix.sync.aligned.m8n8.x2.shared.b16 {%0,%1}, [%2];"
                 : "=r"(r0), "=r"(r1) : "r"(addr));
}
__device__ __forceinline__ void mma_16816(float* c, uint32_t a0, uint32_t a1,
                                          uint32_t a2, uint32_t a3,
                                          uint32_t b0, uint32_t b1) {
    asm volatile(
        "mma.sync.aligned.m16n8k16.row.col.f32.f16.f16.f32 "
        "{%0,%1,%2,%3}, {%4,%5,%6,%7}, {%8,%9}, {%0,%1,%2,%3};"
        : "+f"(c[0]), "+f"(c[1]), "+f"(c[2]), "+f"(c[3])
        : "r"(a0), "r"(a1), "r"(a2), "r"(a3), "r"(b0), "r"(b1));
}

#define PA 72  // smem pitch in halves: 144B row stride, conflict-free ldmatrix

// ---------------------------------------------------------------------------
// CSR construction, scan-free (segments need not be receiver-ordered).
// ---------------------------------------------------------------------------
__global__ void zero_cnt_kernel(int N) {
    int i = blockIdx.x * blockDim.x + threadIdx.x;
    if (i < N) g_cnt[i] = 0;
    if (i == 0) g_total = 0;
}

__global__ void hist_kernel(const int* __restrict__ ei, int E) {
    int i = blockIdx.x * blockDim.x + threadIdx.x;
    if (i < E) atomicAdd(&g_cnt[__ldg(&ei[E + i])], 1);
}

__global__ void assign_kernel(int N) {
    int i = blockIdx.x * blockDim.x + threadIdx.x;
    if (i < N) {
        int c = g_cnt[i];
        int base = atomicAdd(&g_total, c);
        g_offs[i] = base;
        g_cursor[i] = base;
    }
}

__global__ void scatter_kernel(const int* __restrict__ ei, int E) {
    int i = blockIdx.x * blockDim.x + threadIdx.x;
    if (i < E) {
        int snd = __ldg(&ei[i]);
        int rcv = __ldg(&ei[E + i]);
        int pos = atomicAdd(&g_cursor[rcv], 1);
        g_ssend[pos] = snd;
    }
}

// ---------------------------------------------------------------------------
// Fused QKV projection via HMMA (fp32 accum, fp16 stores).
// ---------------------------------------------------------------------------
__global__ void __launch_bounds__(256) qkv_kernel(
    const float* __restrict__ x,
    const float* __restrict__ Wq,
    const float* __restrict__ Wk,
    const float* __restrict__ Wv, int N) {
    __shared__ __half sA[128 * PA];
    __shared__ __half sW[64 * PA];  // W^T: sW[n][k]

    const int tid = threadIdx.x;
    const int lane = tid & 31;
    const int warp = tid >> 5;
    const int tile0 = blockIdx.x * 128;

    for (int i = tid; i < 128 * 16; i += 256) {
        int row = i >> 4;
        int c4 = i & 15;
        int grow = tile0 + row;
        float4 v = make_float4(0.f, 0.f, 0.f, 0.f);
        if (grow < N) v = reinterpret_cast<const float4*>(x + (size_t)grow * D)[c4];
        __half2 h0 = __floats2half2_rn(v.x, v.y);
        __half2 h1 = __floats2half2_rn(v.z, v.w);
        uint2 pkt = make_uint2(*reinterpret_cast<uint32_t*>(&h0),
                               *reinterpret_cast<uint32_t*>(&h1));
        *reinterpret_cast<uint2*>(&sA[row * PA + c4 * 4]) = pkt;
    }

    const uint32_t sA_u = smem_u32(sA);
    const uint32_t sW_u = smem_u32(sW);

    const int mrow = warp * 16 + (lane & 7) + ((lane >> 3) & 1) * 8;
    const int acol = (lane >> 4) * 8;
    const uint32_t aBase = sA_u + (mrow * PA + acol) * 2;
    const int l15 = lane & 15;
    const int nrow_l = l15 & 7;
    const int bcol = ((l15 >> 3) & 1) * 8;

    const int gid = lane >> 2;
    const int tig = lane & 3;

    const float* Ws[3] = {Wq, Wk, Wv};
    __half* Gs[3] = {g_Qh, g_Kh, g_Vh};

#pragma unroll
    for (int p = 0; p < 3; p++) {
        __syncthreads();
        for (int i = tid; i < 64 * 16; i += 256) {
            int k = i >> 4;
            int c4 = i & 15;
            float4 w = __ldg(reinterpret_cast<const float4*>(Ws[p] + k * D + c4 * 4));
            sW[(c4 * 4 + 0) * PA + k] = __float2half_rn(w.x);
            sW[(c4 * 4 + 1) * PA + k] = __float2half_rn(w.y);
            sW[(c4 * 4 + 2) * PA + k] = __float2half_rn(w.z);
            sW[(c4 * 4 + 3) * PA + k] = __float2half_rn(w.w);
        }
        __syncthreads();

        float acc[8][4];
#pragma unroll
        for (int nt = 0; nt < 8; nt++)
#pragma unroll
            for (int q = 0; q < 4; q++) acc[nt][q] = 0.f;

#pragma unroll
        for (int k = 0; k < 4; k++) {
            uint32_t a0, a1, a2, a3;
            ldsm_x4(a0, a1, a2, a3, aBase + k * 32);
#pragma unroll
            for (int nt = 0; nt < 8; nt++) {
                uint32_t b0, b1;
                ldsm_x2(b0, b1,
                        sW_u + ((nt * 8 + nrow_l) * PA + k * 16 + bcol) * 2);
                mma_16816(acc[nt], a0, a1, a2, a3, b0, b1);
            }
        }

        __half* G = Gs[p];
        int r_lo = tile0 + warp * 16 + gid;
        int r_hi = r_lo + 8;
#pragma unroll
        for (int nt = 0; nt < 8; nt++) {
            int col = nt * 8 + tig * 2;
            if (r_lo < N)
                *reinterpret_cast<__half2*>(G + (size_t)r_lo * D + col) =
                    __floats2half2_rn(acc[nt][0], acc[nt][1]);
            if (r_hi < N)
                *reinterpret_cast<__half2*>(G + (size_t)r_hi * D + col) =
                    __floats2half2_rn(acc[nt][2], acc[nt][3]);
        }
    }
}

// ---------------------------------------------------------------------------
// CSR aggregation, octet-parallel: one warp per receiver, 4 edges in flight
// (8 lanes per edge, uint4 fp16 loads). 3 shfl/edge in-loop; one cross-octet
// reduction (18 shfl) per receiver. fp32 register accumulation, no atomics.
// ---------------------------------------------------------------------------
__global__ void __launch_bounds__(256) aggregate_kernel(int N) {
    int wg = (blockIdx.x * blockDim.x + threadIdx.x) >> 5;
    int lane = threadIdx.x & 31;
    if (wg >= N) return;
    int rcv = wg;
    int oct = lane >> 3;   // 0..3 : which edge of the quad
    int ol = lane & 7;     // 0..7 : 8 halves of the row

    int start = g_offs[rcv];
    int cnt = g_cnt[rcv];
    int end = start + cnt;

    // Q row: each lane holds halves [ol*8, ol*8+8) (replicated across octets)
    uint4 qu = reinterpret_cast<const uint4*>(g_Qh + (size_t)rcv * D)[ol];
    float2 q0 = __half22float2(*reinterpret_cast<__half2*>(&qu.x));
    float2 q1 = __half22float2(*reinterpret_cast<__half2*>(&qu.y));
    float2 q2 = __half22float2(*reinterpret_cast<__half2*>(&qu.z));
    float2 q3 = __half22float2(*reinterpret_cast<__half2*>(&qu.w));

    float acc[8];
#pragma unroll
    for (int i = 0; i < 8; i++) acc[i] = 0.f;
    float denom = 0.f;

    int iters = (cnt + 3) >> 2;
    for (int it = 0; it < iters; it++) {
        int eb = start + it * 4 + oct;
        bool ok = eb < end;
        int snd = ok ? g_ssend[eb] : 0;

        uint4 ku = reinterpret_cast<const uint4*>(g_Kh + (size_t)snd * D)[ol];
        float2 k0 = __half22float2(*reinterpret_cast<__half2*>(&ku.x));
        float2 k1 = __half22float2(*reinterpret_cast<__half2*>(&ku.y));
        float2 k2 = __half22float2(*reinterpret_cast<__half2*>(&ku.z));
        float2 k3 = __half22float2(*reinterpret_cast<__half2*>(&ku.w));

        float part = q0.x * k0.x + q0.y * k0.y + q1.x * k1.x + q1.y * k1.y
                   + q2.x * k2.x + q2.y * k2.y + q3.x * k3.x + q3.y * k3.y;
        // reduce within octet (xor of bits 0-2 stays inside the octet)
        part += __shfl_xor_sync(0xffffffffu, part, 1);
        part += __shfl_xor_sync(0xffffffffu, part, 2);
        part += __shfl_xor_sync(0xffffffffu, part, 4);

        float p = ok ? __expf(part * SCALE) : 0.f;

        uint4 vu = reinterpret_cast<const uint4*>(g_Vh + (size_t)snd * D)[ol];
        float2 v0 = __half22float2(*reinterpret_cast<__half2*>(&vu.x));
        float2 v1 = __half22float2(*reinterpret_cast<__half2*>(&vu.y));
        float2 v2 = __half22float2(*reinterpret_cast<__half2*>(&vu.z));
        float2 v3 = __half22float2(*reinterpret_cast<__half2*>(&vu.w));

        acc[0] = fmaf(p, v0.x, acc[0]); acc[1] = fmaf(p, v0.y, acc[1]);
        acc[2] = fmaf(p, v1.x, acc[2]); acc[3] = fmaf(p, v1.y, acc[3]);
        acc[4] = fmaf(p, v2.x, acc[4]); acc[5] = fmaf(p, v2.y, acc[5]);
        acc[6] = fmaf(p, v3.x, acc[6]); acc[7] = fmaf(p, v3.y, acc[7]);
        denom += p;
    }

    // cross-octet reduction (lanes with equal ol hold the same dims)
#pragma unroll
    for (int i = 0; i < 8; i++) {
        acc[i] += __shfl_xor_sync(0xffffffffu, acc[i], 8);
        acc[i] += __shfl_xor_sync(0xffffffffu, acc[i], 16);
    }
    denom += __shfl_xor_sync(0xffffffffu, denom, 8);
    denom += __shfl_xor_sync(0xffffffffu, denom, 16);

    if (oct == 0) {
        float inv = denom > 0.f ? 1.0f / denom : 0.f;
        __half2 h0 = __floats2half2_rn(acc[0] * inv, acc[1] * inv);
        __half2 h1 = __floats2half2_rn(acc[2] * inv, acc[3] * inv);
        __half2 h2 = __floats2half2_rn(acc[4] * inv, acc[5] * inv);
        __half2 h3 = __floats2half2_rn(acc[6] * inv, acc[7] * inv);
        uint4 pkt = make_uint4(*reinterpret_cast<uint32_t*>(&h0),
                               *reinterpret_cast<uint32_t*>(&h1),
                               *reinterpret_cast<uint32_t*>(&h2),
                               *reinterpret_cast<uint32_t*>(&h3));
        reinterpret_cast<uint4*>(g_Hh + (size_t)rcv * D)[ol] = pkt;
    }
}

// ---------------------------------------------------------------------------
// Output: out = x + h @ Wo via HMMA (h already fp16+normalized in g_Hh).
// ---------------------------------------------------------------------------
__global__ void __launch_bounds__(256) out_kernel(
    const float* __restrict__ x,
    const float* __restrict__ Wo,
    float* __restrict__ out, int N) {
    __shared__ __half sA[128 * PA];
    __shared__ __half sW[64 * PA];

    const int tid = threadIdx.x;
    const int lane = tid & 31;
    const int warp = tid >> 5;
    const int tile0 = blockIdx.x * 128;

    for (int i = tid; i < 128 * 8; i += 256) {
        int row = i >> 3;
        int c8 = i & 7;
        int grow = tile0 + row;
        uint4 pkt = make_uint4(0u, 0u, 0u, 0u);
        if (grow < N)
            pkt = reinterpret_cast<const uint4*>(g_Hh + (size_t)grow * D)[c8];
        *reinterpret_cast<uint4*>(&sA[row * PA + c8 * 8]) = pkt;
    }
    for (int i = tid; i < 64 * 16; i += 256) {
        int k = i >> 4;
        int c4 = i & 15;
        float4 w = __ldg(reinterpret_cast<const float4*>(Wo + k * D + c4 * 4));
        sW[(c4 * 4 + 0) * PA + k] = __float2half_rn(w.x);
        sW[(c4 * 4 + 1) * PA + k] = __float2half_rn(w.y);
        sW[(c4 * 4 + 2) * PA + k] = __float2half_rn(w.z);
        sW[(c4 * 4 + 3) * PA + k] = __float2half_rn(w.w);
    }
    __syncthreads();

    const uint32_t sA_u = smem_u32(sA);
    const uint32_t sW_u = smem_u32(sW);

    const int mrow = warp * 16 + (lane & 7) + ((lane >> 3) & 1) * 8;
    const int acol = (lane >> 4) * 8;
    const uint32_t aBase = sA_u + (mrow * PA + acol) * 2;
    const int l15 = lane & 15;
    const int nrow_l = l15 & 7;
    const int bcol = ((l15 >> 3) & 1) * 8;

    float acc[8][4];
#pragma unroll
    for (int nt = 0; nt < 8; nt++)
#pragma unroll
        for (int q = 0; q < 4; q++) acc[nt][q] = 0.f;

#pragma unroll
    for (int k = 0; k < 4; k++) {
        uint32_t a0, a1, a2, a3;
        ldsm_x4(a0, a1, a2, a3, aBase + k * 32);
#pragma unroll
        for (int nt = 0; nt < 8; nt++) {
            uint32_t b0, b1;
            ldsm_x2(b0, b1, sW_u + ((nt * 8 + nrow_l) * PA + k * 16 + bcol) * 2);
            mma_16816(acc[nt], a0, a1, a2, a3, b0, b1);
        }
    }

    const int gid = lane >> 2;
    const int tig = lane & 3;
    int r_lo = tile0 + warp * 16 + gid;
    int r_hi = r_lo + 8;
#pragma unroll
    for (int nt = 0; nt < 8; nt++) {
        int col = nt * 8 + tig * 2;
        if (r_lo < N) {
            float2 xr = *reinterpret_cast<const float2*>(x + (size_t)r_lo * D + col);
            *reinterpret_cast<float2*>(out + (size_t)r_lo * D + col) =
                make_float2(xr.x + acc[nt][0], xr.y + acc[nt][1]);
        }
        if (r_hi < N) {
            float2 xr = *reinterpret_cast<const float2*>(x + (size_t)r_hi * D + col);
            *reinterpret_cast<float2*>(out + (size_t)r_hi * D + col) =
                make_float2(xr.x + acc[nt][2], xr.y + acc[nt][3]);
        }
    }
}

// ---------------------------------------------------------------------------
extern "C" void kernel_launch(void* const* d_in, const int* in_sizes, int n_in,
                              void* d_out, int out_size) {
    const float* x  = (const float*)d_in[0];
    const int*   ei = (const int*)d_in[1];
    const float* Wq = (const float*)d_in[2];
    const float* Wk = (const float*)d_in[3];
    const float* Wv = (const float*)d_in[4];
    const float* Wo = (const float*)d_in[5];
    float* out = (float*)d_out;

    int N = in_sizes[0] / D;
    int E = in_sizes[1] / 2;

    int tiles = (N + 127) / 128;

    zero_cnt_kernel<<<(N + 255) / 256, 256>>>(N);
    hist_kernel<<<(E + 255) / 256, 256>>>(ei, E);
    assign_kernel<<<(N + 255) / 256, 256>>>(N);
    scatter_kernel<<<(E + 255) / 256, 256>>>(ei, E);

    qkv_kernel<<<tiles, 256>>>(x, Wq, Wk, Wv, N);
    aggregate_kernel<<<(N * 32 + 255) / 256, 256>>>(N);
    out_kernel<<<tiles, 256>>>(x, Wo, out, N);
}